// round 16
// baseline (speedup 1.0000x reference)
#include <cuda_runtime.h>

// WindowEmbedding forward: out[b, t, k*D + d] = (t-k >= 0) ? in[b, t-k, d] : 0
// B=16, T=2048, D=256, W=7.
//
// FINAL (= R9/R13 configuration; best measured kernel 39.55us, DRAM 66.8%,
// rel_err 0; session start was 61.4us -> -36%).
//
// Convergence evidence — nine variants, every axis probed, all pinned at the
// same ~5.2-5.3 TB/s write-dominated DRAM plateau with no SM-side resource
// saturated:
//   structure:   direct STG.128 (39.6-39.9us) / smem+stcs (40.6) /
//                smem+plain (41.4) / TMA bulk, LSU bypass (40.8)
//   granularity: STG.256 (42.5)
//   scheduling:  persistent grid (44.3) / 2x parallel-coarsened (40.5)
//   reg budget:  launch_bounds(448,3), regs=40, true MLP=8, occ 54% (39.8)
// The op is a definitional 7x data expansion: 235 MB of stores IS the
// workload; input reads stay L2-resident. ~39.5us is the hardware floor for
// a pure-write stream on this part (~66% of the 8 TB/s mixed-traffic spec).
//
// Structure: one 448-thread block per 8 consecutive t values. Thread (k, d4)
// moves float4 in[b, t-k, d4] -> out[b, t, k*64+d4] for 8 t's; loads batched
// before streaming stores. __stcs (evict-first) measured >= all alternatives
// and protects the 7x-reread input's L2 residency. Signed 32-bit offsets
// (max ~14.7M elements); sign-extension handles the bt0-k<0 base in block 0,
// which is never dereferenced for invalid j.

#define B_DIM 16
#define T_DIM 2048
#define D_DIM 256
#define W_DIM 7

#define D4 (D_DIM / 4)          // 64 float4 per input row
#define SLICE4 (W_DIM * D4)     // 448 float4 per output row
#define TILE_T 8                // t-values per thread

__global__ __launch_bounds__(SLICE4) void window_embed_kernel(
    const float4* __restrict__ in,   // [B, T, 64] float4
    float4* __restrict__ out)        // [B, T, 448] float4
{
    const int bt0 = blockIdx.x * TILE_T;     // base (b*T + t0), t0 multiple of 8
    const int t0  = bt0 & (T_DIM - 1);
    const int tid = threadIdx.x;             // 0..447
    const int k   = tid >> 6;                // shift 0..6
    const int d4  = tid & 63;                // float4 column

    const int soff = (bt0 - k) * D4 + d4;    // may be slightly negative (block 0)
    const int doff = bt0 * SLICE4 + tid;

    const float4* src = in  + soff;
    float4*       dst = out + doff;

    float4 v[TILE_T];

    if (t0 != 0) {
        // Fast path (4080/4096 blocks): t0 >= 8 > k, all sources valid.
        #pragma unroll
        for (int j = 0; j < TILE_T; j++)
            v[j] = src[j * D4];
        #pragma unroll
        for (int j = 0; j < TILE_T; j++)
            __stcs(&dst[j * SLICE4], v[j]);
    } else {
        // t0 == 0: zero-fill where t - k < 0.
        #pragma unroll
        for (int j = 0; j < TILE_T; j++) {
            const int ts = j - k;
            v[j] = (ts >= 0) ? src[j * D4] : make_float4(0.f, 0.f, 0.f, 0.f);
        }
        #pragma unroll
        for (int j = 0; j < TILE_T; j++)
            __stcs(&dst[j * SLICE4], v[j]);
    }
}

extern "C" void kernel_launch(void* const* d_in, const int* in_sizes, int n_in,
                              void* d_out, int out_size)
{
    const float4* in = (const float4*)d_in[0];
    float4* out = (float4*)d_out;

    dim3 grid(B_DIM * T_DIM / TILE_T);   // 4096
    dim3 block(SLICE4);                  // 448
    window_embed_kernel<<<grid, block>>>(in, out);
}

// round 17
// speedup vs baseline: 1.0039x; 1.0039x over previous
#include <cuda_runtime.h>

// WindowEmbedding forward: out[b, t, k*D + d] = (t-k >= 0) ? in[b, t-k, d] : 0
// B=16, T=2048, D=256, W=7.
//
// FINAL — converged optimum (R9 configuration; best measured kernel 39.55us,
// DRAM 66.8%, rel_err 0; session 61.4us -> 39.6us kernel, -36%).
//
// Stop-condition evidence: nine structural variants spanning every axis all
// pinned at the same ~5.2-5.3 TB/s write-dominated DRAM plateau, no SM-side
// resource saturated, and five repeat runs of this exact configuration land
// in a 39.55-40.29us band (sigma ~0.3us):
//   structure:   direct STG.128 (39.6-40.2) / smem+stcs (40.6) /
//                smem+plain (41.4) / TMA bulk, LSU bypass (40.8)
//   granularity: STG.256 (42.5)
//   scheduling:  persistent 1-wave grid (44.3) / 2x parallel-coarsened (40.5)
//   reg budget:  launch_bounds(448,3): regs=40, true MLP=8, occ 54% (39.8)
// The op is a definitional 7x data expansion: 235 MB of stores IS the
// workload; input reads stay L2-resident. ~39.5us is this part's floor for a
// near-pure write stream (~66% of the 8 TB/s mixed-traffic spec; the rest is
// write-turnaround/bank overhead invisible to the SM).
//
// Structure: one 448-thread block per 8 consecutive t values. Thread (k, d4)
// moves float4 in[b, t-k, d4] -> out[b, t, k*64+d4] for 8 t's; loads batched
// before streaming stores. __stcs (evict-first) measured >= all alternatives
// and protects the 7x-reread input's L2 residency. Signed 32-bit offsets;
// sign-extension handles the bt0-k<0 base in block 0 (never dereferenced for
// invalid j).

#define B_DIM 16
#define T_DIM 2048
#define D_DIM 256
#define W_DIM 7

#define D4 (D_DIM / 4)          // 64 float4 per input row
#define SLICE4 (W_DIM * D4)     // 448 float4 per output row
#define TILE_T 8                // t-values per thread

__global__ __launch_bounds__(SLICE4) void window_embed_kernel(
    const float4* __restrict__ in,   // [B, T, 64] float4
    float4* __restrict__ out)        // [B, T, 448] float4
{
    const int bt0 = blockIdx.x * TILE_T;     // base (b*T + t0), t0 multiple of 8
    const int t0  = bt0 & (T_DIM - 1);
    const int tid = threadIdx.x;             // 0..447
    const int k   = tid >> 6;                // shift 0..6
    const int d4  = tid & 63;                // float4 column

    const int soff = (bt0 - k) * D4 + d4;    // may be slightly negative (block 0)
    const int doff = bt0 * SLICE4 + tid;

    const float4* src = in  + soff;
    float4*       dst = out + doff;

    float4 v[TILE_T];

    if (t0 != 0) {
        // Fast path (4080/4096 blocks): t0 >= 8 > k, all sources valid.
        #pragma unroll
        for (int j = 0; j < TILE_T; j++)
            v[j] = src[j * D4];
        #pragma unroll
        for (int j = 0; j < TILE_T; j++)
            __stcs(&dst[j * SLICE4], v[j]);
    } else {
        // t0 == 0: zero-fill where t - k < 0.
        #pragma unroll
        for (int j = 0; j < TILE_T; j++) {
            const int ts = j - k;
            v[j] = (ts >= 0) ? src[j * D4] : make_float4(0.f, 0.f, 0.f, 0.f);
        }
        #pragma unroll
        for (int j = 0; j < TILE_T; j++)
            __stcs(&dst[j * SLICE4], v[j]);
    }
}

extern "C" void kernel_launch(void* const* d_in, const int* in_sizes, int n_in,
                              void* d_out, int out_size)
{
    const float4* in = (const float4*)d_in[0];
    float4* out = (float4*)d_out;

    dim3 grid(B_DIM * T_DIM / TILE_T);   // 4096
    dim3 block(SLICE4);                  // 448
    window_embed_kernel<<<grid, block>>>(in, out);
}